// round 1
// baseline (speedup 1.0000x reference)
#include <cuda_runtime.h>
#include <cstdint>
#include <cstring>
#include <cmath>
#include <vector>
#include <algorithm>
#include <utility>

// ============================================================================
// Problem constants
// ============================================================================
#define BB 4
#define NPTS 4096

// JAX threefry mode: 1 = partitionable (default since jax 0.4.36), 0 = original
#define JAX_THREEFRY_PARTITIONABLE 1

// ============================================================================
// Device scratch (static allocations — allowed; no runtime alloc)
// ============================================================================
__device__ float g_fo [(size_t)BB * NPTS * 576];   // largest fo buffer (stage A)
__device__ float g_fm1[(size_t)BB * NPTS * 64];
__device__ float g_fm2[(size_t)BB * NPTS * 64];
__device__ float g_va [(size_t)BB * 512 * 3];
__device__ float g_vb [(size_t)BB * 64 * 3];
__device__ float g_vanchor[(size_t)BB * 512 * 3];
__device__ int   g_idx [(size_t)BB * NPTS * 20];
__device__ int   g_idx8[(size_t)BB * 512 * 8];
__device__ int   g_perm1[512];
__device__ int   g_perm2[64];
__device__ int   g_perm3[8];

struct PermParams {
    int p1[512];
    int p2[64];
    int p3[8];
};

__global__ void init_perms(PermParams pp) {
    int t = blockIdx.x * blockDim.x + threadIdx.x;
    if (t < 512) g_perm1[t] = pp.p1[t];
    if (t < 64)  g_perm2[t] = pp.p2[t];
    if (t < 8)   g_perm3[t] = pp.p3[t];
}

// ============================================================================
// KNN: brute force, one thread per query; coords staged in shared memory.
// KK = k+1 (self included). Emulates lax.top_k(-dist, k+1)[..., 1:]:
// ascending (dist, idx) with stable tie-break (lower idx first), drop slot 0.
// dist = sq_i - 2*inner + sq_j  (matches reference formula & eval order).
// ============================================================================
template<int KK>
__global__ void knn_kernel(const float* __restrict__ v, int n,
                           const int* __restrict__ qmap, int nq,
                           int* __restrict__ idx_out) {
    extern __shared__ float sc[];   // n*3 floats
    int b = blockIdx.y;
    const float* vb = v + (size_t)b * n * 3;
    for (int i = threadIdx.x; i < n * 3; i += blockDim.x) sc[i] = vb[i];
    __syncthreads();

    int q = blockIdx.x * blockDim.x + threadIdx.x;
    if (q >= nq) return;
    int qi = qmap ? qmap[q] : q;

    float qx = sc[qi*3+0], qy = sc[qi*3+1], qz = sc[qi*3+2];
    float sqq = qx*qx + qy*qy + qz*qz;

    float bd[KK]; int bi[KK];
    #pragma unroll
    for (int t = 0; t < KK; t++) { bd[t] = INFINITY; bi[t] = -1; }

    for (int j = 0; j < n; j++) {
        float x = sc[j*3+0], y = sc[j*3+1], z = sc[j*3+2];
        float inner = fmaf(qz, z, fmaf(qy, y, qx * x));
        float sqj = x*x + y*y + z*z;
        float d = sqq - 2.0f * inner + sqj;
        if (d < bd[KK-1]) {           // equal-to-last rejected => lower idx kept
            bd[KK-1] = d; bi[KK-1] = j;
            #pragma unroll
            for (int t = KK - 2; t >= 0; t--) {
                if (bd[t+1] < bd[t]) {   // strict: ties keep earlier index first
                    float td = bd[t]; bd[t] = bd[t+1]; bd[t+1] = td;
                    int   ti = bi[t]; bi[t] = bi[t+1]; bi[t+1] = ti;
                }
            }
        }
    }
    int* orow = idx_out + ((size_t)b * nq + q) * (KK - 1);
    #pragma unroll
    for (int t = 1; t < KK; t++) orow[t-1] = bi[t];
}

// ============================================================================
// op3d (stage A only): fm = relu( sum_s( max_k relu(nd @ d0) * w0 ) )
// block = one point (256 threads = 256 theta channels), k = 20, out 32 ch.
// ============================================================================
__global__ void op3d_kernel(const int* __restrict__ idx, const float* __restrict__ v,
                            const float* __restrict__ d0, const float* __restrict__ w0,
                            float* __restrict__ fm, int n, int k) {
    __shared__ float snd[20 * 3];
    __shared__ float sh[256];
    int b = blockIdx.y, i = blockIdx.x, t = threadIdx.x;
    const float* vb = v + (size_t)b * n * 3;
    if (t < k) {
        int nb = idx[((size_t)b * n + i) * k + t];
        snd[t*3+0] = vb[nb*3+0] - vb[i*3+0];
        snd[t*3+1] = vb[nb*3+1] - vb[i*3+1];
        snd[t*3+2] = vb[nb*3+2] - vb[i*3+2];
    }
    __syncthreads();
    float e0 = d0[t], e1 = d0[256 + t], e2 = d0[512 + t];
    float m = -INFINITY;
    for (int j = 0; j < k; j++) {
        float th = fmaf(snd[3*j+2], e2, fmaf(snd[3*j+1], e1, snd[3*j] * e0));
        th = fmaxf(th, 0.0f);
        m = fmaxf(m, th);
    }
    sh[t] = m * w0[t];
    __syncthreads();
    if (t < 32) {
        float s = sh[t];
        #pragma unroll
        for (int ss = 1; ss < 8; ss++) s += sh[ss * 32 + t];
        fm[((size_t)b * n + i) * 32 + t] = fmaxf(s, 0.0f);
    }
}

// ============================================================================
// fo = A @ W + bias.  A: [M,K] (M multiple of 16), W: [K,C], out: [M,C].
// Block: 16 rows x 256 cols; A tile transposed in smem ([K][16]).
// ============================================================================
__global__ void gemm_bias(const float* __restrict__ A, const float* __restrict__ W,
                          const float* __restrict__ bias, float* __restrict__ out,
                          int M, int K, int C) {
    extern __shared__ float sA[];   // K*16
    int row0 = blockIdx.y * 16;
    int c = blockIdx.x * 256 + threadIdx.x;
    for (int i = threadIdx.x; i < 16 * K; i += 256) {
        int r = i / K, kk = i - r * K;
        sA[kk * 16 + r] = A[(size_t)(row0 + r) * K + kk];
    }
    __syncthreads();
    if (c >= C) return;
    float acc[16];
    float bv = bias[c];
    #pragma unroll
    for (int r = 0; r < 16; r++) acc[r] = bv;
    for (int kk = 0; kk < K; kk++) {
        float w = W[(size_t)kk * C + c];
        const float* a = sA + kk * 16;
        #pragma unroll
        for (int r = 0; r < 16; r++) acc[r] = fmaf(a[r], w, acc[r]);
    }
    #pragma unroll
    for (int r = 0; r < 16; r++) out[(size_t)(row0 + r) * C + c] = acc[r];
}

// ============================================================================
// opnd: out = maybe_relu( fo[:, :oc]  +  sum_s max_k( relu(nd@dw) * fo_gather ) )
// block = one point; CH = 8*oc channels strided over threads; neighbor max in
// a single register per channel; S-reduction through smax[] in shared.
// ============================================================================
__global__ void opnd_kernel(const int* __restrict__ idx, const float* __restrict__ v,
                            const float* __restrict__ fo, const float* __restrict__ dw,
                            float* __restrict__ out, int n, int k, int oc, int do_relu) {
    extern __shared__ float sm[];
    float* snd  = sm;                      // 3k floats
    int*   sidx = (int*)(sm + 3 * k);      // k ints
    float* smax = sm + 4 * k;              // 8*oc floats
    int b = blockIdx.y, i = blockIdx.x, t = threadIdx.x;
    int CH = 8 * oc, FR = 9 * oc;
    const float* vb = v + (size_t)b * n * 3;
    if (t < k) {
        int nb = idx[((size_t)b * n + i) * k + t];
        sidx[t] = nb;
        snd[t*3+0] = vb[nb*3+0] - vb[i*3+0];
        snd[t*3+1] = vb[nb*3+1] - vb[i*3+1];
        snd[t*3+2] = vb[nb*3+2] - vb[i*3+2];
    }
    __syncthreads();
    const float* fob = fo + (size_t)b * n * FR;
    for (int c = t; c < CH; c += blockDim.x) {
        float e0 = dw[c], e1 = dw[CH + c], e2 = dw[2 * CH + c];
        float m = -INFINITY;
        for (int j = 0; j < k; j++) {
            float th = fmaf(snd[3*j+2], e2, fmaf(snd[3*j+1], e1, snd[3*j] * e0));
            th = fmaxf(th, 0.0f);
            float supp = fob[(size_t)sidx[j] * FR + oc + c];
            m = fmaxf(m, th * supp);
        }
        smax[c] = m;
    }
    __syncthreads();
    for (int c = t; c < oc; c += blockDim.x) {
        float s = smax[c];
        #pragma unroll
        for (int ss = 1; ss < 8; ss++) s += smax[ss * oc + c];
        float r = fob[(size_t)i * FR + c] + s;
        out[((size_t)b * n + i) * oc + c] = do_relu ? fmaxf(r, 0.0f) : r;
    }
}

// ============================================================================
// pool gather: fm_out[b,p,:] = max over 8 knn-neighbors of fm_in; v gather.
// ============================================================================
__global__ void poolgather(const int* __restrict__ idx8, const float* __restrict__ fm_in,
                           const float* __restrict__ v_in, const int* __restrict__ perm,
                           float* __restrict__ fm_out, float* __restrict__ v_out,
                           float* __restrict__ vanchor, int n_in, int nq, int C) {
    __shared__ int sj[8];
    int b = blockIdx.y, p = blockIdx.x, t = threadIdx.x;
    if (t < 8) sj[t] = idx8[((size_t)b * nq + p) * 8 + t];
    __syncthreads();
    for (int c = t; c < C; c += blockDim.x) {
        float m = -INFINITY;
        #pragma unroll
        for (int j = 0; j < 8; j++)
            m = fmaxf(m, fm_in[((size_t)b * n_in + sj[j]) * C + c]);
        fm_out[((size_t)b * nq + p) * C + c] = m;
    }
    if (t < 3) {
        int src = perm[p];
        float val = v_in[((size_t)b * n_in + src) * 3 + t];
        v_out[((size_t)b * nq + p) * 3 + t] = val;
        if (vanchor) vanchor[((size_t)b * nq + p) * 3 + t] = val;
    }
}

// ============================================================================
// finalize: out[0:4096] = fm.max over the 8 points; out[4096:10240] = v_anchor
// ============================================================================
__global__ void finalize_kernel(const float* __restrict__ fm,
                                const float* __restrict__ vanchor,
                                float* __restrict__ out) {
    int t = blockIdx.x * blockDim.x + threadIdx.x;
    if (t < BB * 1024) {
        int b = t >> 10, c = t & 1023;
        float m = -INFINITY;
        #pragma unroll
        for (int j = 0; j < 8; j++)
            m = fmaxf(m, fm[((size_t)b * 8 + j) * 1024 + c]);
        out[t] = m;
    } else if (t < BB * 1024 + BB * 512 * 3) {
        out[t] = vanchor[t - BB * 1024];
    }
}

// ============================================================================
// Host: bit-exact JAX threefry2x32 PRNG + permutation
// ============================================================================
static inline uint32_t rotl32(uint32_t x, int d) { return (x << d) | (x >> (32 - d)); }

static void tf2x32(uint32_t k0, uint32_t k1, uint32_t c0, uint32_t c1,
                   uint32_t& o0, uint32_t& o1) {
    uint32_t ks0 = k0, ks1 = k1, ks2 = k0 ^ k1 ^ 0x1BD11BDAu;
    uint32_t x0 = c0 + ks0, x1 = c1 + ks1;
    static const int R0[4] = {13, 15, 26, 6};
    static const int R1[4] = {17, 29, 16, 24};
    uint32_t ks[3] = {ks0, ks1, ks2};
    for (int d = 0; d < 5; d++) {
        const int* r = (d & 1) ? R1 : R0;
        for (int j = 0; j < 4; j++) { x0 += x1; x1 = rotl32(x1, r[j]); x1 ^= x0; }
        x0 += ks[(d + 1) % 3];
        x1 += ks[(d + 2) % 3] + (uint32_t)(d + 1);
    }
    o0 = x0; o1 = x1;
}

// JAX _shuffle: sort arange by random 32-bit keys, num_rounds = ceil(3 ln n / ln(2^32-1))
static void jax_perm(uint32_t k0, uint32_t k1, int n, std::vector<int>& x) {
    x.resize(n);
    for (int i = 0; i < n; i++) x[i] = i;
    int rounds = (int)ceil(3.0 * log((double)n) / log(4294967295.0));
    std::vector<std::pair<uint32_t, int>> kv(n);
#if JAX_THREEFRY_PARTITIONABLE
    for (int r = 0; r < rounds; r++) {
        uint32_t nk0, nk1, sk0, sk1;
        tf2x32(k0, k1, 0u, 0u, nk0, nk1);     // split: newkey = tf(key,(0,0))
        tf2x32(k0, k1, 0u, 1u, sk0, sk1);     //        subkey = tf(key,(0,1))
        k0 = nk0; k1 = nk1;
        for (int i = 0; i < n; i++) {
            uint32_t o0, o1;
            tf2x32(sk0, sk1, 0u, (uint32_t)i, o0, o1);
            kv[i] = { o0 ^ o1, x[i] };        // 32-bit bits = out1 ^ out2
        }
        std::stable_sort(kv.begin(), kv.end(),
                         [](const std::pair<uint32_t,int>& a, const std::pair<uint32_t,int>& b)
                         { return a.first < b.first; });
        for (int i = 0; i < n; i++) x[i] = kv[i].second;
    }
#else
    for (int r = 0; r < rounds; r++) {
        // split(key,2): counts [0,1,2,3] -> pairs (0,2),(1,3)
        uint32_t a0, b0, a1, b1;
        tf2x32(k0, k1, 0u, 2u, a0, b0);
        tf2x32(k0, k1, 1u, 3u, a1, b1);
        // newkey=(o0(0,2),o0(1,3)), subkey=(o1(0,2),o1(1,3))
        uint32_t sk0 = b0, sk1 = b1;
        k0 = a0; k1 = a1;
        // bits: counts 0..n-1 -> pairs (i, i+n/2)
        std::vector<uint32_t> bits(n);
        for (int i = 0; i < n / 2; i++) {
            uint32_t o0, o1;
            tf2x32(sk0, sk1, (uint32_t)i, (uint32_t)(i + n / 2), o0, o1);
            bits[i] = o0; bits[i + n / 2] = o1;
        }
        for (int i = 0; i < n; i++) kv[i] = { bits[i], x[i] };
        std::stable_sort(kv.begin(), kv.end(),
                         [](const std::pair<uint32_t,int>& a, const std::pair<uint32_t,int>& b)
                         { return a.first < b.first; });
        for (int i = 0; i < n; i++) x[i] = kv[i].second;
    }
#endif
}

static void compute_perm_params(PermParams& pp) {
    // base key = jax.random.key(42) -> (0, 42); split into 3 keys
    uint32_t K0 = 0u, K1 = 42u;
    uint32_t keys[3][2];
#if JAX_THREEFRY_PARTITIONABLE
    for (int i = 0; i < 3; i++)
        tf2x32(K0, K1, 0u, (uint32_t)i, keys[i][0], keys[i][1]);
#else
    {
        // counts 0..5 -> pairs (0,3),(1,4),(2,5); concat [o0s..., o1s...]; reshape(3,2)
        uint32_t r[6];
        tf2x32(K0, K1, 0u, 3u, r[0], r[3]);
        tf2x32(K0, K1, 1u, 4u, r[1], r[4]);
        tf2x32(K0, K1, 2u, 5u, r[2], r[5]);
        keys[0][0] = r[0]; keys[0][1] = r[1];
        keys[1][0] = r[2]; keys[1][1] = r[3];
        keys[2][0] = r[4]; keys[2][1] = r[5];
    }
#endif
    std::vector<int> p;
    jax_perm(keys[0][0], keys[0][1], 4096, p);
    for (int i = 0; i < 512; i++) pp.p1[i] = p[i];
    jax_perm(keys[1][0], keys[1][1], 512, p);
    for (int i = 0; i < 64; i++) pp.p2[i] = p[i];
    jax_perm(keys[2][0], keys[2][1], 64, p);
    for (int i = 0; i < 8; i++) pp.p3[i] = p[i];
}

// ============================================================================
// kernel_launch
// ============================================================================
extern "C" void kernel_launch(void* const* d_in, const int* in_sizes, int n_in,
                              void* d_out, int out_size) {
    (void)in_sizes; (void)n_in; (void)out_size;

    const float* verts = (const float*)d_in[0];
    const float* w0 = (const float*)d_in[1];
    const float* d0 = (const float*)d_in[2];
    const float *W[7], *Bi[7], *Dw[7];
    for (int i = 1; i <= 6; i++) {
        W[i]  = (const float*)d_in[3 * i + 0];
        Bi[i] = (const float*)d_in[3 * i + 1];
        Dw[i] = (const float*)d_in[3 * i + 2];
    }

    // device scratch addresses
    float *fo, *fm1, *fm2, *va, *vb, *vanchor;
    int *idx, *idx8, *perm1, *perm2, *perm3;
    cudaGetSymbolAddress((void**)&fo,  g_fo);
    cudaGetSymbolAddress((void**)&fm1, g_fm1);
    cudaGetSymbolAddress((void**)&fm2, g_fm2);
    cudaGetSymbolAddress((void**)&va,  g_va);
    cudaGetSymbolAddress((void**)&vb,  g_vb);
    cudaGetSymbolAddress((void**)&vanchor, g_vanchor);
    cudaGetSymbolAddress((void**)&idx,  g_idx);
    cudaGetSymbolAddress((void**)&idx8, g_idx8);
    cudaGetSymbolAddress((void**)&perm1, g_perm1);
    cudaGetSymbolAddress((void**)&perm2, g_perm2);
    cudaGetSymbolAddress((void**)&perm3, g_perm3);

    // permutations (deterministic, recomputed every call)
    PermParams pp;
    compute_perm_params(pp);
    init_perms<<<2, 256>>>(pp);

    // ---- Stage A (n=4096) ----
    knn_kernel<21><<<dim3(32, BB), 128, NPTS * 3 * 4>>>(verts, 4096, nullptr, 4096, idx);
    op3d_kernel<<<dim3(4096, BB), 256>>>(idx, verts, d0, w0, fm1, 4096, 20);
    gemm_bias<<<dim3(3, 16384 / 16), 256, 16 * 32 * 4>>>(fm1, W[1], Bi[1], fo, 16384, 32, 576);
    opnd_kernel<<<dim3(4096, BB), 256, (4 * 20 + 512) * 4>>>(idx, verts, fo, Dw[1], fm2, 4096, 20, 64, 1);
    knn_kernel<9><<<dim3(4, BB), 128, NPTS * 3 * 4>>>(verts, 4096, perm1, 512, idx8);
    poolgather<<<dim3(512, BB), 128>>>(idx8, fm2, verts, perm1, fm1, va, vanchor, 4096, 512, 64);

    // ---- Stage B (n=512) ----
    knn_kernel<21><<<dim3(4, BB), 128, 512 * 3 * 4>>>(va, 512, nullptr, 512, idx);
    gemm_bias<<<dim3(5, 2048 / 16), 256, 16 * 64 * 4>>>(fm1, W[2], Bi[2], fo, 2048, 64, 1152);
    opnd_kernel<<<dim3(512, BB), 256, (4 * 20 + 1024) * 4>>>(idx, va, fo, Dw[2], fm2, 512, 20, 128, 1);
    gemm_bias<<<dim3(9, 2048 / 16), 256, 16 * 128 * 4>>>(fm2, W[3], Bi[3], fo, 2048, 128, 2304);
    opnd_kernel<<<dim3(512, BB), 256, (4 * 20 + 2048) * 4>>>(idx, va, fo, Dw[3], fm1, 512, 20, 256, 1);
    knn_kernel<9><<<dim3(1, BB), 128, 512 * 3 * 4>>>(va, 512, perm2, 64, idx8);
    poolgather<<<dim3(64, BB), 128>>>(idx8, fm1, va, perm2, fm2, vb, nullptr, 512, 64, 256);

    // ---- Stage C (n=64) ----
    knn_kernel<21><<<dim3(1, BB), 128, 64 * 3 * 4>>>(vb, 64, nullptr, 64, idx);
    gemm_bias<<<dim3(18, 256 / 16), 256, 16 * 256 * 4>>>(fm2, W[4], Bi[4], fo, 256, 256, 4608);
    opnd_kernel<<<dim3(64, BB), 256, (4 * 20 + 4096) * 4>>>(idx, vb, fo, Dw[4], fm1, 64, 20, 512, 1);
    gemm_bias<<<dim3(18, 256 / 16), 256, 16 * 512 * 4>>>(fm1, W[5], Bi[5], fo, 256, 512, 4608);
    opnd_kernel<<<dim3(64, BB), 256, (4 * 20 + 4096) * 4>>>(idx, vb, fo, Dw[5], fm2, 64, 20, 512, 1);
    knn_kernel<9><<<dim3(1, BB), 128, 64 * 3 * 4>>>(vb, 64, perm3, 8, idx8);
    poolgather<<<dim3(8, BB), 128>>>(idx8, fm2, vb, perm3, fm1, va, nullptr, 64, 8, 512);

    // ---- Stage D (n=8, k=3) ----
    knn_kernel<4><<<dim3(1, BB), 128, 8 * 3 * 4>>>(va, 8, nullptr, 8, idx);
    gemm_bias<<<dim3(36, 32 / 16), 256, 16 * 512 * 4>>>(fm1, W[6], Bi[6], fo, 32, 512, 9216);
    opnd_kernel<<<dim3(8, BB), 256, (4 * 3 + 8192) * 4>>>(idx, va, fo, Dw[6], fm2, 8, 3, 1024, 0);

    finalize_kernel<<<40, 256>>>(fm2, vanchor, (float*)d_out);
}

// round 6
// speedup vs baseline: 1.2767x; 1.2767x over previous
#include <cuda_runtime.h>
#include <cstdint>
#include <cstring>
#include <cmath>
#include <vector>
#include <algorithm>
#include <utility>

// ============================================================================
// Problem constants
// ============================================================================
#define BB 4
#define NPTS 4096

// ============================================================================
// Device scratch
// ============================================================================
__device__ float g_fo [(size_t)BB * NPTS * 576];
__device__ float g_fm1[(size_t)BB * NPTS * 64];
__device__ float g_fm2[(size_t)BB * NPTS * 64];
__device__ float g_va [(size_t)BB * 512 * 3];
__device__ float g_vb [(size_t)BB * 64 * 3];
__device__ float g_vanchor[(size_t)BB * 512 * 3];
__device__ int   g_idx [(size_t)BB * NPTS * 20];
__device__ int   g_idx8[(size_t)BB * 512 * 8];
__device__ int   g_perm1[512];
__device__ int   g_perm2[64];
__device__ int   g_perm3[8];

struct PermParams {
    int p1[512];
    int p2[64];
    int p3[8];
};

__global__ void init_perms(PermParams pp) {
    int t = blockIdx.x * blockDim.x + threadIdx.x;
    if (t < 512) g_perm1[t] = pp.p1[t];
    if (t < 64)  g_perm2[t] = pp.p2[t];
    if (t < 8)   g_perm3[t] = pp.p3[t];
}

// ============================================================================
// KNN: brute force, one thread per query; candidates staged in shared memory
// in chunks of 1024 as float4 (x, y, z, |v|^2).
// Emulates lax.top_k(-dist, k+1)[..., 1:] with stable lower-index tie-break.
// dist = sq_i - 2*inner + sq_j  (same expressions as the round-1 passing
// version — do not change, numerics must match top_k tie behavior).
// ============================================================================
#define KNN_CHUNK 1024

template<int KK>
__global__ void knn_kernel(const float* __restrict__ v, int n,
                           const int* __restrict__ qmap, int nq,
                           int* __restrict__ idx_out) {
    __shared__ float4 sc[KNN_CHUNK];
    int b = blockIdx.y;
    const float* vb = v + (size_t)b * n * 3;

    int q = blockIdx.x * blockDim.x + threadIdx.x;
    bool active = (q < nq);
    int qi = 0;
    if (active) qi = qmap ? qmap[q] : q;

    float qx = vb[qi*3+0], qy = vb[qi*3+1], qz = vb[qi*3+2];
    float sqq = qx*qx + qy*qy + qz*qz;

    float bd[KK]; int bi[KK];
    #pragma unroll
    for (int t = 0; t < KK; t++) { bd[t] = INFINITY; bi[t] = -1; }

    for (int c0 = 0; c0 < n; c0 += KNN_CHUNK) {
        int m = n - c0; if (m > KNN_CHUNK) m = KNN_CHUNK;
        for (int i = threadIdx.x; i < m; i += blockDim.x) {
            float x = vb[(c0+i)*3+0], y = vb[(c0+i)*3+1], z = vb[(c0+i)*3+2];
            sc[i] = make_float4(x, y, z, x*x + y*y + z*z);
        }
        __syncthreads();
        if (active) {
            for (int j = 0; j < m; j++) {
                float4 p = sc[j];
                float inner = fmaf(qz, p.z, fmaf(qy, p.y, qx * p.x));
                float d = sqq - 2.0f * inner + p.w;
                if (d < bd[KK-1]) {
                    bd[KK-1] = d; bi[KK-1] = c0 + j;
                    #pragma unroll
                    for (int t = KK - 2; t >= 0; t--) {
                        if (bd[t+1] < bd[t]) {
                            float td = bd[t]; bd[t] = bd[t+1]; bd[t+1] = td;
                            int   ti = bi[t]; bi[t] = bi[t+1]; bi[t+1] = ti;
                        }
                    }
                }
            }
        }
        __syncthreads();
    }
    if (active) {
        int* orow = idx_out + ((size_t)b * nq + q) * (KK - 1);
        #pragma unroll
        for (int t = 1; t < KK; t++) orow[t-1] = bi[t];
    }
}

// ============================================================================
// op3d (stage A): fm = relu( sum_s( max_k relu(nd @ d0) * w0 ) )
// ============================================================================
__global__ void op3d_kernel(const int* __restrict__ idx, const float* __restrict__ v,
                            const float* __restrict__ d0, const float* __restrict__ w0,
                            float* __restrict__ fm, int n, int k) {
    __shared__ float snd[20 * 3];
    __shared__ float sh[256];
    int b = blockIdx.y, i = blockIdx.x, t = threadIdx.x;
    const float* vb = v + (size_t)b * n * 3;
    if (t < k) {
        int nb = idx[((size_t)b * n + i) * k + t];
        snd[t*3+0] = vb[nb*3+0] - vb[i*3+0];
        snd[t*3+1] = vb[nb*3+1] - vb[i*3+1];
        snd[t*3+2] = vb[nb*3+2] - vb[i*3+2];
    }
    __syncthreads();
    float e0 = d0[t], e1 = d0[256 + t], e2 = d0[512 + t];
    float m = -INFINITY;
    for (int j = 0; j < k; j++) {
        float th = fmaf(snd[3*j+2], e2, fmaf(snd[3*j+1], e1, snd[3*j] * e0));
        th = fmaxf(th, 0.0f);
        m = fmaxf(m, th);
    }
    sh[t] = m * w0[t];
    __syncthreads();
    if (t < 32) {
        float s = sh[t];
        #pragma unroll
        for (int ss = 1; ss < 8; ss++) s += sh[ss * 32 + t];
        fm[((size_t)b * n + i) * 32 + t] = fmaxf(s, 0.0f);
    }
}

// ============================================================================
// Tiled GEMM: out[M,C] = A[M,K] @ W[K,C] + bias.
// 64x64 tile per 256-thread block, K-step 16, 4x4 micro-tile per thread.
// Requires: K % 16 == 0, C % 64 == 0 (all shapes here satisfy this).
// M guarded (stage D has M=32).
// ============================================================================
__global__ void gemm_bias_tiled(const float* __restrict__ A, const float* __restrict__ W,
                                const float* __restrict__ bias, float* __restrict__ out,
                                int M, int K, int C) {
    __shared__ float As[16][68];
    __shared__ float Bs[16][68];
    int tx = threadIdx.x & 15, ty = threadIdx.x >> 4;
    int row0 = blockIdx.y * 64, col0 = blockIdx.x * 64;

    float acc[4][4];
    #pragma unroll
    for (int i = 0; i < 4; i++)
        #pragma unroll
        for (int j = 0; j < 4; j++) acc[i][j] = 0.0f;

    int ar = threadIdx.x >> 2;             // 0..63 row within tile
    int akq = (threadIdx.x & 3) * 4;       // 0,4,8,12 k-quad
    int bk = threadIdx.x >> 4;             // 0..15 k row
    int bcq = (threadIdx.x & 15) * 4;      // 0..60 col quad

    for (int k0 = 0; k0 < K; k0 += 16) {
        float4 a = make_float4(0.f, 0.f, 0.f, 0.f);
        if (row0 + ar < M)
            a = *(const float4*)&A[(size_t)(row0 + ar) * K + k0 + akq];
        As[akq+0][ar] = a.x;
        As[akq+1][ar] = a.y;
        As[akq+2][ar] = a.z;
        As[akq+3][ar] = a.w;
        float4 bvv = *(const float4*)&W[(size_t)(k0 + bk) * C + col0 + bcq];
        *(float4*)&Bs[bk][bcq] = bvv;
        __syncthreads();
        #pragma unroll
        for (int kk = 0; kk < 16; kk++) {
            float4 av = *(const float4*)&As[kk][ty * 4];
            float4 bv = *(const float4*)&Bs[kk][tx * 4];
            acc[0][0] = fmaf(av.x, bv.x, acc[0][0]);
            acc[0][1] = fmaf(av.x, bv.y, acc[0][1]);
            acc[0][2] = fmaf(av.x, bv.z, acc[0][2]);
            acc[0][3] = fmaf(av.x, bv.w, acc[0][3]);
            acc[1][0] = fmaf(av.y, bv.x, acc[1][0]);
            acc[1][1] = fmaf(av.y, bv.y, acc[1][1]);
            acc[1][2] = fmaf(av.y, bv.z, acc[1][2]);
            acc[1][3] = fmaf(av.y, bv.w, acc[1][3]);
            acc[2][0] = fmaf(av.z, bv.x, acc[2][0]);
            acc[2][1] = fmaf(av.z, bv.y, acc[2][1]);
            acc[2][2] = fmaf(av.z, bv.z, acc[2][2]);
            acc[2][3] = fmaf(av.z, bv.w, acc[2][3]);
            acc[3][0] = fmaf(av.w, bv.x, acc[3][0]);
            acc[3][1] = fmaf(av.w, bv.y, acc[3][1]);
            acc[3][2] = fmaf(av.w, bv.z, acc[3][2]);
            acc[3][3] = fmaf(av.w, bv.w, acc[3][3]);
        }
        __syncthreads();
    }

    float4 bias4 = *(const float4*)&bias[col0 + tx * 4];
    #pragma unroll
    for (int i = 0; i < 4; i++) {
        int row = row0 + ty * 4 + i;
        if (row < M) {
            float4 o;
            o.x = acc[i][0] + bias4.x;
            o.y = acc[i][1] + bias4.y;
            o.z = acc[i][2] + bias4.z;
            o.w = acc[i][3] + bias4.w;
            *(float4*)&out[(size_t)row * C + col0 + tx * 4] = o;
        }
    }
}

// ============================================================================
// opnd (float4 channels):
// out = maybe_relu( fo[:, :oc] + sum_s max_k( relu(nd@dw) * fo_gather ) )
// dw layout is [3][CH]; per-channel c: theta = dx*dw[0][c]+dy*dw[1][c]+dz*dw[2][c].
// ============================================================================
__global__ void opnd_kernel(const int* __restrict__ idx, const float* __restrict__ v,
                            const float* __restrict__ fo, const float* __restrict__ dw,
                            float* __restrict__ out, int n, int k, int oc, int do_relu) {
    extern __shared__ float sm[];
    float* snd  = sm;                      // 3k floats
    int*   sidx = (int*)(sm + 3 * k);      // k ints
    float* smax = sm + 4 * k;              // 8*oc floats (16B aligned for k=20,3)
    int b = blockIdx.y, i = blockIdx.x, t = threadIdx.x;
    int CH = 8 * oc, CH4 = CH >> 2, FR = 9 * oc;
    const float* vb = v + (size_t)b * n * 3;
    if (t < k) {
        int nb = idx[((size_t)b * n + i) * k + t];
        sidx[t] = nb;
        snd[t*3+0] = vb[nb*3+0] - vb[i*3+0];
        snd[t*3+1] = vb[nb*3+1] - vb[i*3+1];
        snd[t*3+2] = vb[nb*3+2] - vb[i*3+2];
    }
    __syncthreads();
    const float* fob = fo + (size_t)b * n * FR;
    const float4* dw4 = (const float4*)dw;
    float4* smax4 = (float4*)smax;
    for (int c4 = t; c4 < CH4; c4 += blockDim.x) {
        float4 e0 = dw4[c4], e1 = dw4[CH4 + c4], e2 = dw4[2 * CH4 + c4];
        float4 m = make_float4(-INFINITY, -INFINITY, -INFINITY, -INFINITY);
        for (int j = 0; j < k; j++) {
            float dx = snd[3*j], dy = snd[3*j+1], dz = snd[3*j+2];
            const float4 supp = *(const float4*)&fob[(size_t)sidx[j] * FR + oc + c4 * 4];
            float tx0 = fmaxf(fmaf(dz, e2.x, fmaf(dy, e1.x, dx * e0.x)), 0.0f);
            float tx1 = fmaxf(fmaf(dz, e2.y, fmaf(dy, e1.y, dx * e0.y)), 0.0f);
            float tx2 = fmaxf(fmaf(dz, e2.z, fmaf(dy, e1.z, dx * e0.z)), 0.0f);
            float tx3 = fmaxf(fmaf(dz, e2.w, fmaf(dy, e1.w, dx * e0.w)), 0.0f);
            m.x = fmaxf(m.x, tx0 * supp.x);
            m.y = fmaxf(m.y, tx1 * supp.y);
            m.z = fmaxf(m.z, tx2 * supp.z);
            m.w = fmaxf(m.w, tx3 * supp.w);
        }
        smax4[c4] = m;
    }
    __syncthreads();
    int oc4 = oc >> 2;
    for (int c4 = t; c4 < oc4; c4 += blockDim.x) {
        float4 s = smax4[c4];
        #pragma unroll
        for (int ss = 1; ss < 8; ss++) {
            float4 v2 = smax4[ss * oc4 + c4];
            s.x += v2.x; s.y += v2.y; s.z += v2.z; s.w += v2.w;
        }
        float4 ctr = *(const float4*)&fob[(size_t)i * FR + c4 * 4];
        float4 r;
        r.x = ctr.x + s.x; r.y = ctr.y + s.y; r.z = ctr.z + s.z; r.w = ctr.w + s.w;
        if (do_relu) {
            r.x = fmaxf(r.x, 0.f); r.y = fmaxf(r.y, 0.f);
            r.z = fmaxf(r.z, 0.f); r.w = fmaxf(r.w, 0.f);
        }
        *(float4*)&out[(((size_t)b * n + i) * oc) + c4 * 4] = r;
    }
}

// ============================================================================
// pool gather (float4 channels)
// ============================================================================
__global__ void poolgather(const int* __restrict__ idx8, const float* __restrict__ fm_in,
                           const float* __restrict__ v_in, const int* __restrict__ perm,
                           float* __restrict__ fm_out, float* __restrict__ v_out,
                           float* __restrict__ vanchor, int n_in, int nq, int C) {
    __shared__ int sj[8];
    int b = blockIdx.y, p = blockIdx.x, t = threadIdx.x;
    if (t < 8) sj[t] = idx8[((size_t)b * nq + p) * 8 + t];
    __syncthreads();
    int C4 = C >> 2;
    const float4* fi = (const float4*)(fm_in + (size_t)b * n_in * C);
    float4* fot = (float4*)(fm_out + ((size_t)b * nq + p) * C);
    for (int c4 = t; c4 < C4; c4 += blockDim.x) {
        float4 m = make_float4(-INFINITY, -INFINITY, -INFINITY, -INFINITY);
        #pragma unroll
        for (int j = 0; j < 8; j++) {
            float4 x = fi[(size_t)sj[j] * C4 + c4];
            m.x = fmaxf(m.x, x.x); m.y = fmaxf(m.y, x.y);
            m.z = fmaxf(m.z, x.z); m.w = fmaxf(m.w, x.w);
        }
        fot[c4] = m;
    }
    if (t < 3) {
        int src = perm[p];
        float val = v_in[((size_t)b * n_in + src) * 3 + t];
        v_out[((size_t)b * nq + p) * 3 + t] = val;
        if (vanchor) vanchor[((size_t)b * nq + p) * 3 + t] = val;
    }
}

// ============================================================================
// finalize: out[0:4096] = fm.max over the 8 points; out[4096:10240] = v_anchor
// ============================================================================
__global__ void finalize_kernel(const float* __restrict__ fm,
                                const float* __restrict__ vanchor,
                                float* __restrict__ out) {
    int t = blockIdx.x * blockDim.x + threadIdx.x;
    if (t < BB * 1024) {
        int b = t >> 10, c = t & 1023;
        float m = -INFINITY;
        #pragma unroll
        for (int j = 0; j < 8; j++)
            m = fmaxf(m, fm[((size_t)b * 8 + j) * 1024 + c]);
        out[t] = m;
    } else if (t < BB * 1024 + BB * 512 * 3) {
        out[t] = vanchor[t - BB * 1024];
    }
}

// ============================================================================
// Host: bit-exact JAX threefry2x32 PRNG + permutation (partitionable path)
// ============================================================================
static inline uint32_t rotl32(uint32_t x, int d) { return (x << d) | (x >> (32 - d)); }

static void tf2x32(uint32_t k0, uint32_t k1, uint32_t c0, uint32_t c1,
                   uint32_t& o0, uint32_t& o1) {
    uint32_t ks0 = k0, ks1 = k1, ks2 = k0 ^ k1 ^ 0x1BD11BDAu;
    uint32_t x0 = c0 + ks0, x1 = c1 + ks1;
    static const int R0[4] = {13, 15, 26, 6};
    static const int R1[4] = {17, 29, 16, 24};
    uint32_t ks[3] = {ks0, ks1, ks2};
    for (int d = 0; d < 5; d++) {
        const int* r = (d & 1) ? R1 : R0;
        for (int j = 0; j < 4; j++) { x0 += x1; x1 = rotl32(x1, r[j]); x1 ^= x0; }
        x0 += ks[(d + 1) % 3];
        x1 += ks[(d + 2) % 3] + (uint32_t)(d + 1);
    }
    o0 = x0; o1 = x1;
}

static void jax_perm(uint32_t k0, uint32_t k1, int n, std::vector<int>& x) {
    x.resize(n);
    for (int i = 0; i < n; i++) x[i] = i;
    int rounds = (int)ceil(3.0 * log((double)n) / log(4294967295.0));
    std::vector<std::pair<uint32_t, int>> kv(n);
    for (int r = 0; r < rounds; r++) {
        uint32_t nk0, nk1, sk0, sk1;
        tf2x32(k0, k1, 0u, 0u, nk0, nk1);
        tf2x32(k0, k1, 0u, 1u, sk0, sk1);
        k0 = nk0; k1 = nk1;
        for (int i = 0; i < n; i++) {
            uint32_t o0, o1;
            tf2x32(sk0, sk1, 0u, (uint32_t)i, o0, o1);
            kv[i] = { o0 ^ o1, x[i] };
        }
        std::stable_sort(kv.begin(), kv.end(),
                         [](const std::pair<uint32_t,int>& a, const std::pair<uint32_t,int>& b)
                         { return a.first < b.first; });
        for (int i = 0; i < n; i++) x[i] = kv[i].second;
    }
}

static void compute_perm_params(PermParams& pp) {
    uint32_t K0 = 0u, K1 = 42u;
    uint32_t keys[3][2];
    for (int i = 0; i < 3; i++)
        tf2x32(K0, K1, 0u, (uint32_t)i, keys[i][0], keys[i][1]);
    std::vector<int> p;
    jax_perm(keys[0][0], keys[0][1], 4096, p);
    for (int i = 0; i < 512; i++) pp.p1[i] = p[i];
    jax_perm(keys[1][0], keys[1][1], 512, p);
    for (int i = 0; i < 64; i++) pp.p2[i] = p[i];
    jax_perm(keys[2][0], keys[2][1], 64, p);
    for (int i = 0; i < 8; i++) pp.p3[i] = p[i];
}

// ============================================================================
// kernel_launch
// ============================================================================
extern "C" void kernel_launch(void* const* d_in, const int* in_sizes, int n_in,
                              void* d_out, int out_size) {
    (void)in_sizes; (void)n_in; (void)out_size;

    const float* verts = (const float*)d_in[0];
    const float* w0 = (const float*)d_in[1];
    const float* d0 = (const float*)d_in[2];
    const float *W[7], *Bi[7], *Dw[7];
    for (int i = 1; i <= 6; i++) {
        W[i]  = (const float*)d_in[3 * i + 0];
        Bi[i] = (const float*)d_in[3 * i + 1];
        Dw[i] = (const float*)d_in[3 * i + 2];
    }

    float *fo, *fm1, *fm2, *va, *vb, *vanchor;
    int *idx, *idx8, *perm1, *perm2, *perm3;
    cudaGetSymbolAddress((void**)&fo,  g_fo);
    cudaGetSymbolAddress((void**)&fm1, g_fm1);
    cudaGetSymbolAddress((void**)&fm2, g_fm2);
    cudaGetSymbolAddress((void**)&va,  g_va);
    cudaGetSymbolAddress((void**)&vb,  g_vb);
    cudaGetSymbolAddress((void**)&vanchor, g_vanchor);
    cudaGetSymbolAddress((void**)&idx,  g_idx);
    cudaGetSymbolAddress((void**)&idx8, g_idx8);
    cudaGetSymbolAddress((void**)&perm1, g_perm1);
    cudaGetSymbolAddress((void**)&perm2, g_perm2);
    cudaGetSymbolAddress((void**)&perm3, g_perm3);

    PermParams pp;
    compute_perm_params(pp);
    init_perms<<<2, 256>>>(pp);

    // ---- Stage A (n=4096) ----
    knn_kernel<21><<<dim3(16, BB), 256>>>(verts, 4096, nullptr, 4096, idx);
    op3d_kernel<<<dim3(4096, BB), 256>>>(idx, verts, d0, w0, fm1, 4096, 20);
    gemm_bias_tiled<<<dim3(576/64, 16384/64), 256>>>(fm1, W[1], Bi[1], fo, 16384, 32, 576);
    opnd_kernel<<<dim3(4096, BB), 128, (4*20 + 512)*4>>>(idx, verts, fo, Dw[1], fm2, 4096, 20, 64, 1);
    knn_kernel<9><<<dim3(2, BB), 256>>>(verts, 4096, perm1, 512, idx8);
    poolgather<<<dim3(512, BB), 128>>>(idx8, fm2, verts, perm1, fm1, va, vanchor, 4096, 512, 64);

    // ---- Stage B (n=512) ----
    knn_kernel<21><<<dim3(2, BB), 256>>>(va, 512, nullptr, 512, idx);
    gemm_bias_tiled<<<dim3(1152/64, 2048/64), 256>>>(fm1, W[2], Bi[2], fo, 2048, 64, 1152);
    opnd_kernel<<<dim3(512, BB), 256, (4*20 + 1024)*4>>>(idx, va, fo, Dw[2], fm2, 512, 20, 128, 1);
    gemm_bias_tiled<<<dim3(2304/64, 2048/64), 256>>>(fm2, W[3], Bi[3], fo, 2048, 128, 2304);
    opnd_kernel<<<dim3(512, BB), 512, (4*20 + 2048)*4>>>(idx, va, fo, Dw[3], fm1, 512, 20, 256, 1);
    knn_kernel<9><<<dim3(1, BB), 256>>>(va, 512, perm2, 64, idx8);
    poolgather<<<dim3(64, BB), 128>>>(idx8, fm1, va, perm2, fm2, vb, nullptr, 512, 64, 256);

    // ---- Stage C (n=64) ----
    knn_kernel<21><<<dim3(1, BB), 256>>>(vb, 64, nullptr, 64, idx);
    gemm_bias_tiled<<<dim3(4608/64, 256/64), 256>>>(fm2, W[4], Bi[4], fo, 256, 256, 4608);
    opnd_kernel<<<dim3(64, BB), 512, (4*20 + 4096)*4>>>(idx, vb, fo, Dw[4], fm1, 64, 20, 512, 1);
    gemm_bias_tiled<<<dim3(4608/64, 256/64), 256>>>(fm1, W[5], Bi[5], fo, 256, 512, 4608);
    opnd_kernel<<<dim3(64, BB), 512, (4*20 + 4096)*4>>>(idx, vb, fo, Dw[5], fm2, 64, 20, 512, 1);
    knn_kernel<9><<<dim3(1, BB), 256>>>(vb, 64, perm3, 8, idx8);
    poolgather<<<dim3(8, BB), 128>>>(idx8, fm2, vb, perm3, fm1, va, nullptr, 64, 8, 512);

    // ---- Stage D (n=8, k=3) ----
    knn_kernel<4><<<dim3(1, BB), 256>>>(va, 8, nullptr, 8, idx);
    gemm_bias_tiled<<<dim3(9216/64, 1), 256>>>(fm1, W[6], Bi[6], fo, 32, 512, 9216);
    opnd_kernel<<<dim3(8, BB), 1024, (4*3 + 8192)*4>>>(idx, va, fo, Dw[6], fm2, 8, 3, 1024, 0);

    finalize_kernel<<<40, 256>>>(fm2, vanchor, (float*)d_out);
}

// round 7
// speedup vs baseline: 1.5353x; 1.2026x over previous
#include <cuda_runtime.h>
#include <cstdint>
#include <cstring>
#include <cmath>
#include <vector>
#include <algorithm>
#include <utility>

// ============================================================================
// Problem constants
// ============================================================================
#define BB 4
#define NPTS 4096

// ============================================================================
// Device scratch
// ============================================================================
__device__ float g_fo [(size_t)BB * NPTS * 576];
__device__ float g_fm1[(size_t)BB * NPTS * 64];
__device__ float g_fm2[(size_t)BB * NPTS * 64];
__device__ float g_va [(size_t)BB * 512 * 3];
__device__ float g_vb [(size_t)BB * 64 * 3];
__device__ float g_vanchor[(size_t)BB * 512 * 3];
__device__ int   g_idx [(size_t)BB * NPTS * 20];
__device__ int   g_idx8[(size_t)BB * 512 * 8];
__device__ int   g_perm1[512];
__device__ int   g_perm2[64];
__device__ int   g_perm3[8];

struct PermParams {
    int p1[512];
    int p2[64];
    int p3[8];
};

__global__ void init_perms(PermParams pp) {
    int t = blockIdx.x * blockDim.x + threadIdx.x;
    if (t < 512) g_perm1[t] = pp.p1[t];
    if (t < 64)  g_perm2[t] = pp.p2[t];
    if (t < 8)   g_perm3[t] = pp.p3[t];
}

// ============================================================================
// KNN, warp-per-query. Each of the 8 warps in a block owns one query.
// Lanes scan a 32-stride slice of the candidates (staged in smem as
// float4(x,y,z,|v|^2)), keeping a private ascending top-KK list with strict-<
// insertion (stable: lower candidate index wins ties within a lane).
// Then a KK-round warp merge selects the global top-KK by lexicographic
// (dist, idx) min — exactly lax.top_k's stable ordering. Slot 0 (self) dropped.
// Distance expression identical to the previously passing version.
// ============================================================================
#define KNN_CHUNK 1024

template<int KK>
__global__ void knn_warp_kernel(const float* __restrict__ v, int n,
                                const int* __restrict__ qmap, int nq,
                                int* __restrict__ idx_out) {
    __shared__ float4 sc[KNN_CHUNK];
    int b = blockIdx.y;
    const float* vb = v + (size_t)b * n * 3;
    int wid = threadIdx.x >> 5, lane = threadIdx.x & 31;
    int q = blockIdx.x * (blockDim.x >> 5) + wid;
    bool active = (q < nq);
    int qi = active ? (qmap ? qmap[q] : q) : 0;

    float qx = vb[qi*3+0], qy = vb[qi*3+1], qz = vb[qi*3+2];
    float sqq = qx*qx + qy*qy + qz*qz;

    float bd[KK]; int bi[KK];
    #pragma unroll
    for (int t = 0; t < KK; t++) { bd[t] = INFINITY; bi[t] = -1; }

    for (int c0 = 0; c0 < n; c0 += KNN_CHUNK) {
        int m = n - c0; if (m > KNN_CHUNK) m = KNN_CHUNK;
        for (int i = threadIdx.x; i < m; i += blockDim.x) {
            float x = vb[(c0+i)*3+0], y = vb[(c0+i)*3+1], z = vb[(c0+i)*3+2];
            sc[i] = make_float4(x, y, z, x*x + y*y + z*z);
        }
        __syncthreads();
        for (int j = lane; j < m; j += 32) {
            float4 p = sc[j];
            float inner = fmaf(qz, p.z, fmaf(qy, p.y, qx * p.x));
            float d = sqq - 2.0f * inner + p.w;
            if (d < bd[KK-1]) {
                bd[KK-1] = d; bi[KK-1] = c0 + j;
                #pragma unroll
                for (int t = KK - 2; t >= 0; t--) {
                    if (bd[t+1] < bd[t]) {
                        float td = bd[t]; bd[t] = bd[t+1]; bd[t+1] = td;
                        int   ti = bi[t]; bi[t] = bi[t+1]; bi[t+1] = ti;
                    }
                }
            }
        }
        __syncthreads();
    }

    // Warp merge: KK rounds of lexicographic-min selection.
    int keep = -1;
    #pragma unroll
    for (int t = 0; t < KK; t++) {
        float d0 = bd[0]; int i0 = bi[0];
        float dm = d0; int im = i0;
        #pragma unroll
        for (int off = 16; off; off >>= 1) {
            float od = __shfl_xor_sync(0xffffffffu, dm, off);
            int   oi = __shfl_xor_sync(0xffffffffu, im, off);
            if (od < dm || (od == dm && oi < im)) { dm = od; im = oi; }
        }
        if (lane == t) keep = im;
        if (d0 == dm && i0 == im) {   // unique winner (idx unique) pops its head
            #pragma unroll
            for (int s = 0; s < KK - 1; s++) { bd[s] = bd[s+1]; bi[s] = bi[s+1]; }
            bd[KK-1] = INFINITY; bi[KK-1] = -1;
        }
    }
    if (active && lane >= 1 && lane < KK)
        idx_out[((size_t)b * nq + q) * (KK - 1) + lane - 1] = keep;
}

// ============================================================================
// op3d (stage A): fm = relu( sum_s( max_k relu(nd @ d0) * w0 ) )
// ============================================================================
__global__ void op3d_kernel(const int* __restrict__ idx, const float* __restrict__ v,
                            const float* __restrict__ d0, const float* __restrict__ w0,
                            float* __restrict__ fm, int n, int k) {
    __shared__ float snd[20 * 3];
    __shared__ float sh[256];
    int b = blockIdx.y, i = blockIdx.x, t = threadIdx.x;
    const float* vb = v + (size_t)b * n * 3;
    if (t < k) {
        int nb = idx[((size_t)b * n + i) * k + t];
        snd[t*3+0] = vb[nb*3+0] - vb[i*3+0];
        snd[t*3+1] = vb[nb*3+1] - vb[i*3+1];
        snd[t*3+2] = vb[nb*3+2] - vb[i*3+2];
    }
    __syncthreads();
    float e0 = d0[t], e1 = d0[256 + t], e2 = d0[512 + t];
    float m = -INFINITY;
    for (int j = 0; j < k; j++) {
        float th = fmaf(snd[3*j+2], e2, fmaf(snd[3*j+1], e1, snd[3*j] * e0));
        th = fmaxf(th, 0.0f);
        m = fmaxf(m, th);
    }
    sh[t] = m * w0[t];
    __syncthreads();
    if (t < 32) {
        float s = sh[t];
        #pragma unroll
        for (int ss = 1; ss < 8; ss++) s += sh[ss * 32 + t];
        fm[((size_t)b * n + i) * 32 + t] = fmaxf(s, 0.0f);
    }
}

// ============================================================================
// Tiled GEMM: out[M,C] = A[M,K] @ W[K,C] + bias.
// BM x BN tile, 256 threads, TM x TN micro-tile, K-step 8.
// Constraint: (BM/TM)*(BN/TN) == 256. K % 8 == 0, C % BN == 0; M guarded.
// Accumulation order: k ascending (bitwise-stable across configs).
// ============================================================================
template<int BM, int BN, int TM, int TN>
__global__ void gemm_tiled(const float* __restrict__ A, const float* __restrict__ W,
                           const float* __restrict__ bias, float* __restrict__ out,
                           int M, int K, int C) {
    __shared__ float As[8][BM + 4];
    __shared__ float Bs[8][BN + 4];
    constexpr int NX = BN / TN;            // thread cols
    int tx = threadIdx.x % NX, ty = threadIdx.x / NX;
    int row0 = blockIdx.y * BM, col0 = blockIdx.x * BN;

    float acc[TM][TN];
    #pragma unroll
    for (int i = 0; i < TM; i++)
        #pragma unroll
        for (int j = 0; j < TN; j++) acc[i][j] = 0.0f;

    for (int k0 = 0; k0 < K; k0 += 8) {
        // A tile: BM rows x 8 k (2 float4 quads per row)
        for (int i = threadIdx.x; i < BM * 2; i += 256) {
            int r = i >> 1, kq = (i & 1) * 4;
            float4 a = make_float4(0.f, 0.f, 0.f, 0.f);
            if (row0 + r < M)
                a = *(const float4*)&A[(size_t)(row0 + r) * K + k0 + kq];
            As[kq+0][r] = a.x; As[kq+1][r] = a.y;
            As[kq+2][r] = a.z; As[kq+3][r] = a.w;
        }
        // B tile: 8 k-rows x BN cols
        for (int i = threadIdx.x; i < BN * 2; i += 256) {
            int kk = i / (BN / 4), cq = (i % (BN / 4)) * 4;
            *(float4*)&Bs[kk][cq] =
                *(const float4*)&W[(size_t)(k0 + kk) * C + col0 + cq];
        }
        __syncthreads();
        #pragma unroll
        for (int kk = 0; kk < 8; kk++) {
            float av[TM], bv[TN];
            #pragma unroll
            for (int i = 0; i < TM; i += 4) {
                float4 t4 = *(const float4*)&As[kk][ty * TM + i];
                av[i] = t4.x; av[i+1] = t4.y; av[i+2] = t4.z; av[i+3] = t4.w;
            }
            #pragma unroll
            for (int j = 0; j < TN; j += 4) {
                float4 t4 = *(const float4*)&Bs[kk][tx * TN + j];
                bv[j] = t4.x; bv[j+1] = t4.y; bv[j+2] = t4.z; bv[j+3] = t4.w;
            }
            #pragma unroll
            for (int i = 0; i < TM; i++)
                #pragma unroll
                for (int j = 0; j < TN; j++)
                    acc[i][j] = fmaf(av[i], bv[j], acc[i][j]);
        }
        __syncthreads();
    }

    float bvv[TN];
    #pragma unroll
    for (int j = 0; j < TN; j += 4) {
        float4 t4 = *(const float4*)&bias[col0 + tx * TN + j];
        bvv[j] = t4.x; bvv[j+1] = t4.y; bvv[j+2] = t4.z; bvv[j+3] = t4.w;
    }
    #pragma unroll
    for (int i = 0; i < TM; i++) {
        int row = row0 + ty * TM + i;
        if (row < M) {
            #pragma unroll
            for (int j = 0; j < TN; j += 4) {
                float4 o;
                o.x = acc[i][j+0] + bvv[j+0];
                o.y = acc[i][j+1] + bvv[j+1];
                o.z = acc[i][j+2] + bvv[j+2];
                o.w = acc[i][j+3] + bvv[j+3];
                *(float4*)&out[(size_t)row * C + col0 + tx * TN + j] = o;
            }
        }
    }
}

// ============================================================================
// opnd (float4 channels):
// out = maybe_relu( fo[:, :oc] + sum_s max_k( relu(nd@dw) * fo_gather ) )
// ============================================================================
__global__ void opnd_kernel(const int* __restrict__ idx, const float* __restrict__ v,
                            const float* __restrict__ fo, const float* __restrict__ dw,
                            float* __restrict__ out, int n, int k, int oc, int do_relu) {
    extern __shared__ float sm[];
    float* snd  = sm;                      // 3k floats
    int*   sidx = (int*)(sm + 3 * k);      // k ints
    float* smax = sm + 4 * k;              // 8*oc floats (16B aligned for k=20,3)
    int b = blockIdx.y, i = blockIdx.x, t = threadIdx.x;
    int CH = 8 * oc, CH4 = CH >> 2, FR = 9 * oc;
    const float* vb = v + (size_t)b * n * 3;
    if (t < k) {
        int nb = idx[((size_t)b * n + i) * k + t];
        sidx[t] = nb;
        snd[t*3+0] = vb[nb*3+0] - vb[i*3+0];
        snd[t*3+1] = vb[nb*3+1] - vb[i*3+1];
        snd[t*3+2] = vb[nb*3+2] - vb[i*3+2];
    }
    __syncthreads();
    const float* fob = fo + (size_t)b * n * FR;
    const float4* dw4 = (const float4*)dw;
    float4* smax4 = (float4*)smax;
    for (int c4 = t; c4 < CH4; c4 += blockDim.x) {
        float4 e0 = dw4[c4], e1 = dw4[CH4 + c4], e2 = dw4[2 * CH4 + c4];
        float4 m = make_float4(-INFINITY, -INFINITY, -INFINITY, -INFINITY);
        for (int j = 0; j < k; j++) {
            float dx = snd[3*j], dy = snd[3*j+1], dz = snd[3*j+2];
            const float4 supp = *(const float4*)&fob[(size_t)sidx[j] * FR + oc + c4 * 4];
            float tx0 = fmaxf(fmaf(dz, e2.x, fmaf(dy, e1.x, dx * e0.x)), 0.0f);
            float tx1 = fmaxf(fmaf(dz, e2.y, fmaf(dy, e1.y, dx * e0.y)), 0.0f);
            float tx2 = fmaxf(fmaf(dz, e2.z, fmaf(dy, e1.z, dx * e0.z)), 0.0f);
            float tx3 = fmaxf(fmaf(dz, e2.w, fmaf(dy, e1.w, dx * e0.w)), 0.0f);
            m.x = fmaxf(m.x, tx0 * supp.x);
            m.y = fmaxf(m.y, tx1 * supp.y);
            m.z = fmaxf(m.z, tx2 * supp.z);
            m.w = fmaxf(m.w, tx3 * supp.w);
        }
        smax4[c4] = m;
    }
    __syncthreads();
    int oc4 = oc >> 2;
    for (int c4 = t; c4 < oc4; c4 += blockDim.x) {
        float4 s = smax4[c4];
        #pragma unroll
        for (int ss = 1; ss < 8; ss++) {
            float4 v2 = smax4[ss * oc4 + c4];
            s.x += v2.x; s.y += v2.y; s.z += v2.z; s.w += v2.w;
        }
        float4 ctr = *(const float4*)&fob[(size_t)i * FR + c4 * 4];
        float4 r;
        r.x = ctr.x + s.x; r.y = ctr.y + s.y; r.z = ctr.z + s.z; r.w = ctr.w + s.w;
        if (do_relu) {
            r.x = fmaxf(r.x, 0.f); r.y = fmaxf(r.y, 0.f);
            r.z = fmaxf(r.z, 0.f); r.w = fmaxf(r.w, 0.f);
        }
        *(float4*)&out[(((size_t)b * n + i) * oc) + c4 * 4] = r;
    }
}

// ============================================================================
// pool gather (float4 channels)
// ============================================================================
__global__ void poolgather(const int* __restrict__ idx8, const float* __restrict__ fm_in,
                           const float* __restrict__ v_in, const int* __restrict__ perm,
                           float* __restrict__ fm_out, float* __restrict__ v_out,
                           float* __restrict__ vanchor, int n_in, int nq, int C) {
    __shared__ int sj[8];
    int b = blockIdx.y, p = blockIdx.x, t = threadIdx.x;
    if (t < 8) sj[t] = idx8[((size_t)b * nq + p) * 8 + t];
    __syncthreads();
    int C4 = C >> 2;
    const float4* fi = (const float4*)(fm_in + (size_t)b * n_in * C);
    float4* fot = (float4*)(fm_out + ((size_t)b * nq + p) * C);
    for (int c4 = t; c4 < C4; c4 += blockDim.x) {
        float4 m = make_float4(-INFINITY, -INFINITY, -INFINITY, -INFINITY);
        #pragma unroll
        for (int j = 0; j < 8; j++) {
            float4 x = fi[(size_t)sj[j] * C4 + c4];
            m.x = fmaxf(m.x, x.x); m.y = fmaxf(m.y, x.y);
            m.z = fmaxf(m.z, x.z); m.w = fmaxf(m.w, x.w);
        }
        fot[c4] = m;
    }
    if (t < 3) {
        int src = perm[p];
        float val = v_in[((size_t)b * n_in + src) * 3 + t];
        v_out[((size_t)b * nq + p) * 3 + t] = val;
        if (vanchor) vanchor[((size_t)b * nq + p) * 3 + t] = val;
    }
}

// ============================================================================
// finalize: out[0:4096] = fm.max over the 8 points; out[4096:10240] = v_anchor
// ============================================================================
__global__ void finalize_kernel(const float* __restrict__ fm,
                                const float* __restrict__ vanchor,
                                float* __restrict__ out) {
    int t = blockIdx.x * blockDim.x + threadIdx.x;
    if (t < BB * 1024) {
        int b = t >> 10, c = t & 1023;
        float m = -INFINITY;
        #pragma unroll
        for (int j = 0; j < 8; j++)
            m = fmaxf(m, fm[((size_t)b * 8 + j) * 1024 + c]);
        out[t] = m;
    } else if (t < BB * 1024 + BB * 512 * 3) {
        out[t] = vanchor[t - BB * 1024];
    }
}

// ============================================================================
// Host: bit-exact JAX threefry2x32 PRNG + permutation (partitionable path)
// ============================================================================
static inline uint32_t rotl32(uint32_t x, int d) { return (x << d) | (x >> (32 - d)); }

static void tf2x32(uint32_t k0, uint32_t k1, uint32_t c0, uint32_t c1,
                   uint32_t& o0, uint32_t& o1) {
    uint32_t ks0 = k0, ks1 = k1, ks2 = k0 ^ k1 ^ 0x1BD11BDAu;
    uint32_t x0 = c0 + ks0, x1 = c1 + ks1;
    static const int R0[4] = {13, 15, 26, 6};
    static const int R1[4] = {17, 29, 16, 24};
    uint32_t ks[3] = {ks0, ks1, ks2};
    for (int d = 0; d < 5; d++) {
        const int* r = (d & 1) ? R1 : R0;
        for (int j = 0; j < 4; j++) { x0 += x1; x1 = rotl32(x1, r[j]); x1 ^= x0; }
        x0 += ks[(d + 1) % 3];
        x1 += ks[(d + 2) % 3] + (uint32_t)(d + 1);
    }
    o0 = x0; o1 = x1;
}

static void jax_perm(uint32_t k0, uint32_t k1, int n, std::vector<int>& x) {
    x.resize(n);
    for (int i = 0; i < n; i++) x[i] = i;
    int rounds = (int)ceil(3.0 * log((double)n) / log(4294967295.0));
    std::vector<std::pair<uint32_t, int>> kv(n);
    for (int r = 0; r < rounds; r++) {
        uint32_t nk0, nk1, sk0, sk1;
        tf2x32(k0, k1, 0u, 0u, nk0, nk1);
        tf2x32(k0, k1, 0u, 1u, sk0, sk1);
        k0 = nk0; k1 = nk1;
        for (int i = 0; i < n; i++) {
            uint32_t o0, o1;
            tf2x32(sk0, sk1, 0u, (uint32_t)i, o0, o1);
            kv[i] = { o0 ^ o1, x[i] };
        }
        std::stable_sort(kv.begin(), kv.end(),
                         [](const std::pair<uint32_t,int>& a, const std::pair<uint32_t,int>& b)
                         { return a.first < b.first; });
        for (int i = 0; i < n; i++) x[i] = kv[i].second;
    }
}

static void compute_perm_params(PermParams& pp) {
    uint32_t K0 = 0u, K1 = 42u;
    uint32_t keys[3][2];
    for (int i = 0; i < 3; i++)
        tf2x32(K0, K1, 0u, (uint32_t)i, keys[i][0], keys[i][1]);
    std::vector<int> p;
    jax_perm(keys[0][0], keys[0][1], 4096, p);
    for (int i = 0; i < 512; i++) pp.p1[i] = p[i];
    jax_perm(keys[1][0], keys[1][1], 512, p);
    for (int i = 0; i < 64; i++) pp.p2[i] = p[i];
    jax_perm(keys[2][0], keys[2][1], 64, p);
    for (int i = 0; i < 8; i++) pp.p3[i] = p[i];
}

// ============================================================================
// kernel_launch
// ============================================================================
extern "C" void kernel_launch(void* const* d_in, const int* in_sizes, int n_in,
                              void* d_out, int out_size) {
    (void)in_sizes; (void)n_in; (void)out_size;

    const float* verts = (const float*)d_in[0];
    const float* w0 = (const float*)d_in[1];
    const float* d0 = (const float*)d_in[2];
    const float *W[7], *Bi[7], *Dw[7];
    for (int i = 1; i <= 6; i++) {
        W[i]  = (const float*)d_in[3 * i + 0];
        Bi[i] = (const float*)d_in[3 * i + 1];
        Dw[i] = (const float*)d_in[3 * i + 2];
    }

    float *fo, *fm1, *fm2, *va, *vb, *vanchor;
    int *idx, *idx8, *perm1, *perm2, *perm3;
    cudaGetSymbolAddress((void**)&fo,  g_fo);
    cudaGetSymbolAddress((void**)&fm1, g_fm1);
    cudaGetSymbolAddress((void**)&fm2, g_fm2);
    cudaGetSymbolAddress((void**)&va,  g_va);
    cudaGetSymbolAddress((void**)&vb,  g_vb);
    cudaGetSymbolAddress((void**)&vanchor, g_vanchor);
    cudaGetSymbolAddress((void**)&idx,  g_idx);
    cudaGetSymbolAddress((void**)&idx8, g_idx8);
    cudaGetSymbolAddress((void**)&perm1, g_perm1);
    cudaGetSymbolAddress((void**)&perm2, g_perm2);
    cudaGetSymbolAddress((void**)&perm3, g_perm3);

    PermParams pp;
    compute_perm_params(pp);
    init_perms<<<2, 256>>>(pp);

    // ---- Stage A (n=4096) ----
    knn_warp_kernel<21><<<dim3(512, BB), 256>>>(verts, 4096, nullptr, 4096, idx);
    op3d_kernel<<<dim3(4096, BB), 256>>>(idx, verts, d0, w0, fm1, 4096, 20);
    gemm_tiled<128,64,8,4><<<dim3(576/64, 16384/128), 256>>>(fm1, W[1], Bi[1], fo, 16384, 32, 576);
    opnd_kernel<<<dim3(4096, BB), 128, (4*20 + 512)*4>>>(idx, verts, fo, Dw[1], fm2, 4096, 20, 64, 1);
    knn_warp_kernel<9><<<dim3(64, BB), 256>>>(verts, 4096, perm1, 512, idx8);
    poolgather<<<dim3(512, BB), 128>>>(idx8, fm2, verts, perm1, fm1, va, vanchor, 4096, 512, 64);

    // ---- Stage B (n=512) ----
    knn_warp_kernel<21><<<dim3(64, BB), 256>>>(va, 512, nullptr, 512, idx);
    gemm_tiled<128,128,8,8><<<dim3(1152/128, 2048/128), 256>>>(fm1, W[2], Bi[2], fo, 2048, 64, 1152);
    opnd_kernel<<<dim3(512, BB), 256, (4*20 + 1024)*4>>>(idx, va, fo, Dw[2], fm2, 512, 20, 128, 1);
    gemm_tiled<128,128,8,8><<<dim3(2304/128, 2048/128), 256>>>(fm2, W[3], Bi[3], fo, 2048, 128, 2304);
    opnd_kernel<<<dim3(512, BB), 512, (4*20 + 2048)*4>>>(idx, va, fo, Dw[3], fm1, 512, 20, 256, 1);
    knn_warp_kernel<9><<<dim3(8, BB), 256>>>(va, 512, perm2, 64, idx8);
    poolgather<<<dim3(64, BB), 128>>>(idx8, fm1, va, perm2, fm2, vb, nullptr, 512, 64, 256);

    // ---- Stage C (n=64) ----
    knn_warp_kernel<21><<<dim3(8, BB), 256>>>(vb, 64, nullptr, 64, idx);
    gemm_tiled<64,128,4,8><<<dim3(4608/128, 256/64), 256>>>(fm2, W[4], Bi[4], fo, 256, 256, 4608);
    opnd_kernel<<<dim3(64, BB), 512, (4*20 + 4096)*4>>>(idx, vb, fo, Dw[4], fm1, 64, 20, 512, 1);
    gemm_tiled<64,128,4,8><<<dim3(4608/128, 256/64), 256>>>(fm1, W[5], Bi[5], fo, 256, 512, 4608);
    opnd_kernel<<<dim3(64, BB), 512, (4*20 + 4096)*4>>>(idx, vb, fo, Dw[5], fm2, 64, 20, 512, 1);
    knn_warp_kernel<9><<<dim3(1, BB), 256>>>(vb, 64, perm3, 8, idx8);
    poolgather<<<dim3(8, BB), 128>>>(idx8, fm2, vb, perm3, fm1, va, nullptr, 64, 8, 512);

    // ---- Stage D (n=8, k=3) ----
    knn_warp_kernel<4><<<dim3(1, BB), 256>>>(va, 8, nullptr, 8, idx);
    gemm_tiled<64,128,4,8><<<dim3(9216/128, 1), 256>>>(fm1, W[6], Bi[6], fo, 32, 512, 9216);
    opnd_kernel<<<dim3(8, BB), 1024, (4*3 + 8192)*4>>>(idx, va, fo, Dw[6], fm2, 8, 3, 1024, 0);

    finalize_kernel<<<40, 256>>>(fm2, vanchor, (float*)d_out);
}